// round 10
// baseline (speedup 1.0000x reference)
#include <cuda_runtime.h>
#include <math.h>

// Problem constants (fixed by dataset): N=16, C=256, H=W=96, S=9216, masks 48x48.
#define C_DIM 256
#define S_DIM 9216
#define MSK   2304   // 48*48
#define NMAX  16

typedef unsigned long long u64;

// Scratch (device globals; no allocation allowed)
__device__ float g_Sbg[NMAX * C_DIM];
__device__ float g_Sfg[NMAX * C_DIM];
__device__ float g_bf [NMAX * 2 * C_DIM];   // [n][k][c], k=0 bg, k=1 fg
__device__ float g_u  [NMAX * 2 * C_DIM];   // [n][k][c']
__device__ float g_t  [NMAX * 2];
__device__ float g_p  [NMAX * S_DIM];       // attention prob for k=0 (bg)

// packed fp32x2 FMA (Blackwell FFMA2; exact .rn rounding per lane)
#define FMA_F32X2(d, a, b) \
    asm("fma.rn.f32x2 %0, %1, %2, %3;" : "=l"(d) : "l"(a), "l"(b), "l"(d))

// A-row stride (floats). 256 floats = 1024B: every [k][ty*16] offset is
// 16B-aligned, and A reads are warp-broadcast (2 addrs/warp) so no padding
// is needed for bank conflicts. Keeps total static smem at exactly 48KB.
#define AS_STRIDE 256

// ---------------------------------------------------------------------------
// K1: masked spatial sums.  Sbg[n,c] = sum_hw x[n,c,h,w] * bg_up[n,h,w]
// bg_up[h,w] = bg[h/2, w/2] (exact 2x nearest upsample); float4 x loads.
// Block = (cgroup of 8 channels, n). 256 threads.
// ---------------------------------------------------------------------------
__global__ void k1_masked_sums(const float* __restrict__ x,
                               const float* __restrict__ bg,
                               const float* __restrict__ fg) {
    int n  = blockIdx.y;
    int cg = blockIdx.x;           // 0..31, 8 channels each
    int tid = threadIdx.x;

    __shared__ float mbg[MSK];
    __shared__ float mfg[MSK];
    __shared__ float red[16];

    for (int i = tid; i < MSK; i += 256) {
        mbg[i] = bg[n * MSK + i];
        mfg[i] = fg[n * MSK + i];
    }
    __syncthreads();

    for (int cc = 0; cc < 8; ++cc) {
        int c = cg * 8 + cc;
        const float* xp = x + ((size_t)(n * C_DIM + c)) * S_DIM;
        float sb = 0.f, sf = 0.f;
        // 9216/4 = 2304 float4s; rows are 96 wide (divisible by 4) so each
        // float4 stays within one row; mask halves at w>>1 and (w>>1)+1.
        for (int i4 = tid; i4 < S_DIM / 4; i4 += 256) {
            int s = i4 * 4;
            int h = s / 96;
            int w = s - h * 96;
            int mi = (h >> 1) * 48 + (w >> 1);
            float4 xv = *(const float4*)&xp[s];
            float b0 = mbg[mi],     f0 = mfg[mi];
            float b1 = mbg[mi + 1], f1 = mfg[mi + 1];
            sb += (xv.x + xv.y) * b0 + (xv.z + xv.w) * b1;
            sf += (xv.x + xv.y) * f0 + (xv.z + xv.w) * f1;
        }
        #pragma unroll
        for (int o = 16; o > 0; o >>= 1) {
            sb += __shfl_down_sync(0xffffffffu, sb, o);
            sf += __shfl_down_sync(0xffffffffu, sf, o);
        }
        int lane = tid & 31, wp = tid >> 5;
        if (lane == 0) { red[wp] = sb; red[8 + wp] = sf; }
        __syncthreads();
        if (tid == 0) {
            float a = 0.f, b = 0.f;
            #pragma unroll
            for (int i = 0; i < 8; i++) { a += red[i]; b += red[8 + i]; }
            g_Sbg[n * C_DIM + c] = a;
            g_Sfg[n * C_DIM + c] = b;
        }
        __syncthreads();
    }
}

// ---------------------------------------------------------------------------
// helper: block-wide sum with broadcast (blockDim.x == 256)
// ---------------------------------------------------------------------------
__device__ float blockSumBroadcast(float v, float* sm8) {
    #pragma unroll
    for (int o = 16; o > 0; o >>= 1) v += __shfl_xor_sync(0xffffffffu, v, o);
    int wp = threadIdx.x >> 5;
    if ((threadIdx.x & 31) == 0) sm8[wp] = v;
    __syncthreads();
    float tot = 0.f;
    #pragma unroll
    for (int i = 0; i < 8; i++) tot += sm8[i];
    __syncthreads();
    return tot;
}

// ---------------------------------------------------------------------------
// K2: per-n features.  One block per n, 256 threads (thread = channel).
//   bf_k[c] = (W_fb[c,:]·S_k[n,:] + b_fb[c]*M_k) * ratio_k / (H*W)
//   u_k[c'] = sum_o W_v[o,c'] * bf_k[o] ;  t_k = sum_o b_v[o]*bf_k[o]
// ---------------------------------------------------------------------------
__global__ void k2_feats(const float* __restrict__ bg,
                         const float* __restrict__ fg,
                         const float* __restrict__ W_fb,
                         const float* __restrict__ b_fb,
                         const float* __restrict__ W_v,
                         const float* __restrict__ b_v,
                         int N) {
    int n = blockIdx.x;
    int c = threadIdx.x;

    __shared__ float sm8[8];
    __shared__ float sS0[C_DIM], sS1[C_DIM];
    __shared__ float sbf0[C_DIM], sbf1[C_DIM];

    // totals over ALL n (ratio is a global scalar in the reference)
    float tb = 0.f, tf = 0.f;
    int tot = N * MSK;
    for (int i = c; i < tot; i += 256) { tb += bg[i]; tf += fg[i]; }
    float totb = blockSumBroadcast(tb, sm8);
    float totf = blockSumBroadcast(tf, sm8);

    // per-n mask sums
    float nb = 0.f, nf = 0.f;
    for (int i = c; i < MSK; i += 256) { nb += bg[n * MSK + i]; nf += fg[n * MSK + i]; }
    float Mb = 4.f * blockSumBroadcast(nb, sm8);   // upsample replicates 2x2
    float Mf = 4.f * blockSumBroadcast(nf, sm8);

    float ratio_b = ((float)N * (float)S_DIM) / (4.f * totb);
    float ratio_f = ((float)N * (float)S_DIM) / (4.f * totf);

    sS0[c] = g_Sbg[n * C_DIM + c];
    sS1[c] = g_Sfg[n * C_DIM + c];
    __syncthreads();

    float d0 = 0.f, d1 = 0.f;
    const float* wr = W_fb + (size_t)c * C_DIM;
    #pragma unroll 4
    for (int k = 0; k < C_DIM; k++) {
        float w = wr[k];
        d0 += w * sS0[k];
        d1 += w * sS1[k];
    }
    float inv = 1.f / (float)S_DIM;
    float bf0 = (d0 + b_fb[c] * Mb) * inv * ratio_b;
    float bf1 = (d1 + b_fb[c] * Mf) * inv * ratio_f;
    sbf0[c] = bf0; sbf1[c] = bf1;
    g_bf[n * 2 * C_DIM + c]         = bf0;
    g_bf[n * 2 * C_DIM + C_DIM + c] = bf1;
    __syncthreads();

    // u_k[c'] : coalesced column reduction of W_v
    float u0 = 0.f, u1 = 0.f;
    #pragma unroll 4
    for (int o = 0; o < C_DIM; o++) {
        float w = W_v[(size_t)o * C_DIM + c];
        u0 += w * sbf0[o];
        u1 += w * sbf1[o];
    }
    g_u[n * 2 * C_DIM + c]         = u0;
    g_u[n * 2 * C_DIM + C_DIM + c] = u1;

    float t0 = blockSumBroadcast(b_v[c] * sbf0[c], sm8);
    float t1 = blockSumBroadcast(b_v[c] * sbf1[c], sm8);
    if (c == 0) { g_t[n * 2] = t0; g_t[n * 2 + 1] = t1; }
}

// ---------------------------------------------------------------------------
// K2b: attention probability per pixel.
//   l_k = x[:,s]·u_k + t_k ;  p = softmax over 2 -> sigmoid(l0 - l1)
// ---------------------------------------------------------------------------
__global__ void k2b_probs(const float* __restrict__ x) {
    int n = blockIdx.y;
    int s = blockIdx.x * 256 + threadIdx.x;

    __shared__ float sud[C_DIM];   // u0 - u1 (only the difference matters)
    sud[threadIdx.x] = g_u[n * 2 * C_DIM + threadIdx.x]
                     - g_u[n * 2 * C_DIM + C_DIM + threadIdx.x];
    __syncthreads();

    const float* xp = x + (size_t)n * C_DIM * S_DIM + s;
    float a = 0.f;
    #pragma unroll 8
    for (int cc = 0; cc < C_DIM; cc++)
        a += xp[(size_t)cc * S_DIM] * sud[cc];
    float d = a + (g_t[n * 2] - g_t[n * 2 + 1]);
    g_p[n * S_DIM + s] = 1.f / (1.f + expf(-d));
}

// ---------------------------------------------------------------------------
// K3: Y[c,s] = W_f[c,:]·X[:,s] + b_f[c] + gamma*(bf0[c]*p[s] + bf1[c]*(1-p[s]))
// 128x128 tile, BK=16, 256 threads, 8x8 microtile computed as 8x4 f32x2 pairs.
// A stored DUPLICATED in smem ({v,v}) so packed operands load with zero MOVs.
// Double-buffered, register-prefetched, one __syncthreads per K-tile.
// Static smem: As2 32768B + Bs 16384B = 49152B = exactly 48KB.
// ---------------------------------------------------------------------------
__global__ __launch_bounds__(256) void k3_gemm(const float* __restrict__ x,
                                               const float* __restrict__ W_f,
                                               const float* __restrict__ b_f,
                                               const float* __restrict__ gamma,
                                               float* __restrict__ y) {
    int n  = blockIdx.z;
    int c0 = blockIdx.y * 128;
    int s0 = blockIdx.x * 128;
    int tid = threadIdx.x;
    int tx = tid & 15;    // s direction (8 outputs each)
    int ty = tid >> 4;    // c direction (8 outputs each)

    __shared__ __align__(16) float As2[2][16][AS_STRIDE]; // duplicated A pairs
    __shared__ __align__(16) float Bs [2][16][128];       // [buf][k][s]

    u64 acc2[8][4];
    #pragma unroll
    for (int i = 0; i < 8; i++)
        #pragma unroll
        for (int j = 0; j < 4; j++) acc2[i][j] = 0ull;

    const float* xb = x + (size_t)n * C_DIM * S_DIM;

    int a_c0 = (tid >> 2);          // 0..63
    int a_k0 = (tid & 3) * 4;       // 0,4,8,12
    int b_k0 = (tid >> 5);          // 0..7
    int b_s0 = (tid & 31) * 4;      // 0..124

    // ---- preload tile 0 into buffer 0 ----
    #pragma unroll
    for (int r = 0; r < 2; r++) {
        int c_off = r * 64 + a_c0;
        float4 v = *(const float4*)&W_f[(size_t)(c0 + c_off) * C_DIM + a_k0];
        *(float2*)&As2[0][a_k0    ][2 * c_off] = make_float2(v.x, v.x);
        *(float2*)&As2[0][a_k0 + 1][2 * c_off] = make_float2(v.y, v.y);
        *(float2*)&As2[0][a_k0 + 2][2 * c_off] = make_float2(v.z, v.z);
        *(float2*)&As2[0][a_k0 + 3][2 * c_off] = make_float2(v.w, v.w);
    }
    #pragma unroll
    for (int r = 0; r < 2; r++) {
        int kr = r * 8 + b_k0;
        *(float4*)&Bs[0][kr][b_s0] =
            *(const float4*)&xb[(size_t)kr * S_DIM + s0 + b_s0];
    }
    __syncthreads();

    int cur = 0;
    for (int k0 = 0; k0 < C_DIM; k0 += 16) {
        // ---- prefetch next tile into registers ----
        float4 nA[2], nB[2];
        bool has_next = (k0 + 16) < C_DIM;
        if (has_next) {
            int kn = k0 + 16;
            #pragma unroll
            for (int r = 0; r < 2; r++) {
                int c_off = r * 64 + a_c0;
                nA[r] = *(const float4*)&W_f[(size_t)(c0 + c_off) * C_DIM + kn + a_k0];
                int kr = r * 8 + b_k0;
                nB[r] = *(const float4*)&xb[(size_t)(kn + kr) * S_DIM + s0 + b_s0];
            }
        }

        // ---- compute on current buffer (packed f32x2) ----
        #pragma unroll
        for (int k = 0; k < 16; k++) {
            // a: 8 duplicated pairs; 16B-aligned (row stride 1024B); warp sees
            // only 2 distinct addresses (broadcast) -> conflict-free.
            const ulonglong2* apv = (const ulonglong2*)&As2[cur][k][ty * 16];
            ulonglong2 a01 = apv[0], a23 = apv[1], a45 = apv[2], a67 = apv[3];
            u64 ap[8] = {a01.x, a01.y, a23.x, a23.y, a45.x, a45.y, a67.x, a67.y};
            // b: 4 pairs from two 16B loads
            const ulonglong2* bpv = (const ulonglong2*)&Bs[cur][k][tx * 8];
            ulonglong2 b01 = bpv[0], b23 = bpv[1];
            u64 bp[4] = {b01.x, b01.y, b23.x, b23.y};
            #pragma unroll
            for (int i = 0; i < 8; i++)
                #pragma unroll
                for (int j = 0; j < 4; j++)
                    FMA_F32X2(acc2[i][j], ap[i], bp[j]);
        }

        // ---- commit prefetched tile into the other buffer ----
        if (has_next) {
            int nxt = cur ^ 1;
            #pragma unroll
            for (int r = 0; r < 2; r++) {
                int c_off = r * 64 + a_c0;
                float4 v = nA[r];
                *(float2*)&As2[nxt][a_k0    ][2 * c_off] = make_float2(v.x, v.x);
                *(float2*)&As2[nxt][a_k0 + 1][2 * c_off] = make_float2(v.y, v.y);
                *(float2*)&As2[nxt][a_k0 + 2][2 * c_off] = make_float2(v.z, v.z);
                *(float2*)&As2[nxt][a_k0 + 3][2 * c_off] = make_float2(v.w, v.w);
                int kr = r * 8 + b_k0;
                *(float4*)&Bs[nxt][kr][b_s0] = nB[r];
            }
            __syncthreads();
            cur = nxt;
        }
    }

    // ---- fused epilogue ----
    float g = gamma[0];
    float pv[8];
    #pragma unroll
    for (int j = 0; j < 8; j++) pv[j] = g_p[n * S_DIM + s0 + tx * 8 + j];

    #pragma unroll
    for (int i = 0; i < 8; i++) {
        int c = c0 + ty * 8 + i;
        float f0 = g_bf[n * 2 * C_DIM + c];
        float f1 = g_bf[n * 2 * C_DIM + C_DIM + c];
        float bias = b_f[c];
        float* yp = y + ((size_t)(n * C_DIM + c)) * S_DIM + s0 + tx * 8;
        float out8[8];
        #pragma unroll
        for (int j = 0; j < 4; j++) {
            u64 v = acc2[i][j];
            out8[2 * j]     = __uint_as_float((unsigned)(v & 0xffffffffull));
            out8[2 * j + 1] = __uint_as_float((unsigned)(v >> 32));
        }
        #pragma unroll
        for (int j = 0; j < 8; j++) {
            float mixv = f0 * pv[j] + f1 * (1.f - pv[j]);
            yp[j] = out8[j] + bias + g * mixv;
        }
    }
}

// ---------------------------------------------------------------------------
extern "C" void kernel_launch(void* const* d_in, const int* in_sizes, int n_in,
                              void* d_out, int out_size) {
    const float* x     = (const float*)d_in[0];
    const float* bg    = (const float*)d_in[1];
    const float* fg    = (const float*)d_in[2];
    const float* W_fb  = (const float*)d_in[3];
    const float* b_fb  = (const float*)d_in[4];
    const float* W_v   = (const float*)d_in[5];
    const float* b_v   = (const float*)d_in[6];
    const float* W_f   = (const float*)d_in[7];
    const float* b_f   = (const float*)d_in[8];
    const float* gamma = (const float*)d_in[9];
    float* y = (float*)d_out;

    int N = in_sizes[0] / (C_DIM * S_DIM);

    k1_masked_sums<<<dim3(32, N), 256>>>(x, bg, fg);
    k2_feats<<<N, 256>>>(bg, fg, W_fb, b_fb, W_v, b_v, N);
    k2b_probs<<<dim3(S_DIM / 256, N), 256>>>(x);
    k3_gemm<<<dim3(S_DIM / 128, C_DIM / 128, N), 256>>>(x, W_f, b_f, gamma, y);
}

// round 13
// speedup vs baseline: 1.1018x; 1.1018x over previous
#include <cuda_runtime.h>
#include <math.h>

// Problem constants (fixed by dataset): N=16, C=256, H=W=96, S=9216, masks 48x48.
#define C_DIM 256
#define S_DIM 9216
#define MSK   2304   // 48*48
#define NMAX  16

typedef unsigned long long u64;

// Scratch (device globals; no allocation allowed)
__device__ float g_Sbg[NMAX * C_DIM];
__device__ float g_Sfg[NMAX * C_DIM];
__device__ float g_bf [NMAX * 2 * C_DIM];   // [n][k][c], k=0 bg, k=1 fg
__device__ float g_u  [NMAX * 2 * C_DIM];   // [n][k][c']
__device__ float g_t  [NMAX * 2];
__device__ float g_p  [NMAX * S_DIM];       // attention prob for k=0 (bg)

// packed fp32x2 FMA (Blackwell FFMA2; exact .rn rounding per lane)
#define FMA_F32X2(d, a, b) \
    asm("fma.rn.f32x2 %0, %1, %2, %3;" : "=l"(d) : "l"(a), "l"(b), "l"(d))

// A-row stride (floats). 256 floats = 1024B: every 16B read offset stays
// aligned for all k; A reads are few-addr broadcasts (no conflicts).
// Static smem stays at exactly 48KB.
#define AS_STRIDE 256

// ---------------------------------------------------------------------------
// K1: masked spatial sums.  Sbg[n,c] = sum_hw x[n,c,h,w] * bg_up[n,h,w]
// ---------------------------------------------------------------------------
__global__ void k1_masked_sums(const float* __restrict__ x,
                               const float* __restrict__ bg,
                               const float* __restrict__ fg) {
    int n  = blockIdx.y;
    int cg = blockIdx.x;           // 0..31, 8 channels each
    int tid = threadIdx.x;

    __shared__ float mbg[MSK];
    __shared__ float mfg[MSK];
    __shared__ float red[16];

    for (int i = tid; i < MSK; i += 256) {
        mbg[i] = bg[n * MSK + i];
        mfg[i] = fg[n * MSK + i];
    }
    __syncthreads();

    for (int cc = 0; cc < 8; ++cc) {
        int c = cg * 8 + cc;
        const float* xp = x + ((size_t)(n * C_DIM + c)) * S_DIM;
        float sb = 0.f, sf = 0.f;
        for (int i4 = tid; i4 < S_DIM / 4; i4 += 256) {
            int s = i4 * 4;
            int h = s / 96;
            int w = s - h * 96;
            int mi = (h >> 1) * 48 + (w >> 1);
            float4 xv = *(const float4*)&xp[s];
            float b0 = mbg[mi],     f0 = mfg[mi];
            float b1 = mbg[mi + 1], f1 = mfg[mi + 1];
            sb += (xv.x + xv.y) * b0 + (xv.z + xv.w) * b1;
            sf += (xv.x + xv.y) * f0 + (xv.z + xv.w) * f1;
        }
        #pragma unroll
        for (int o = 16; o > 0; o >>= 1) {
            sb += __shfl_down_sync(0xffffffffu, sb, o);
            sf += __shfl_down_sync(0xffffffffu, sf, o);
        }
        int lane = tid & 31, wp = tid >> 5;
        if (lane == 0) { red[wp] = sb; red[8 + wp] = sf; }
        __syncthreads();
        if (tid == 0) {
            float a = 0.f, b = 0.f;
            #pragma unroll
            for (int i = 0; i < 8; i++) { a += red[i]; b += red[8 + i]; }
            g_Sbg[n * C_DIM + c] = a;
            g_Sfg[n * C_DIM + c] = b;
        }
        __syncthreads();
    }
}

// ---------------------------------------------------------------------------
__device__ float blockSumBroadcast(float v, float* sm8) {
    #pragma unroll
    for (int o = 16; o > 0; o >>= 1) v += __shfl_xor_sync(0xffffffffu, v, o);
    int wp = threadIdx.x >> 5;
    if ((threadIdx.x & 31) == 0) sm8[wp] = v;
    __syncthreads();
    float tot = 0.f;
    #pragma unroll
    for (int i = 0; i < 8; i++) tot += sm8[i];
    __syncthreads();
    return tot;
}

// ---------------------------------------------------------------------------
// K2: per-n features.
// ---------------------------------------------------------------------------
__global__ void k2_feats(const float* __restrict__ bg,
                         const float* __restrict__ fg,
                         const float* __restrict__ W_fb,
                         const float* __restrict__ b_fb,
                         const float* __restrict__ W_v,
                         const float* __restrict__ b_v,
                         int N) {
    int n = blockIdx.x;
    int c = threadIdx.x;

    __shared__ float sm8[8];
    __shared__ float sS0[C_DIM], sS1[C_DIM];
    __shared__ float sbf0[C_DIM], sbf1[C_DIM];

    float tb = 0.f, tf = 0.f;
    int tot = N * MSK;
    for (int i = c; i < tot; i += 256) { tb += bg[i]; tf += fg[i]; }
    float totb = blockSumBroadcast(tb, sm8);
    float totf = blockSumBroadcast(tf, sm8);

    float nb = 0.f, nf = 0.f;
    for (int i = c; i < MSK; i += 256) { nb += bg[n * MSK + i]; nf += fg[n * MSK + i]; }
    float Mb = 4.f * blockSumBroadcast(nb, sm8);
    float Mf = 4.f * blockSumBroadcast(nf, sm8);

    float ratio_b = ((float)N * (float)S_DIM) / (4.f * totb);
    float ratio_f = ((float)N * (float)S_DIM) / (4.f * totf);

    sS0[c] = g_Sbg[n * C_DIM + c];
    sS1[c] = g_Sfg[n * C_DIM + c];
    __syncthreads();

    float d0 = 0.f, d1 = 0.f;
    const float* wr = W_fb + (size_t)c * C_DIM;
    #pragma unroll 4
    for (int k = 0; k < C_DIM; k++) {
        float w = wr[k];
        d0 += w * sS0[k];
        d1 += w * sS1[k];
    }
    float inv = 1.f / (float)S_DIM;
    float bf0 = (d0 + b_fb[c] * Mb) * inv * ratio_b;
    float bf1 = (d1 + b_fb[c] * Mf) * inv * ratio_f;
    sbf0[c] = bf0; sbf1[c] = bf1;
    g_bf[n * 2 * C_DIM + c]         = bf0;
    g_bf[n * 2 * C_DIM + C_DIM + c] = bf1;
    __syncthreads();

    float u0 = 0.f, u1 = 0.f;
    #pragma unroll 4
    for (int o = 0; o < C_DIM; o++) {
        float w = W_v[(size_t)o * C_DIM + c];
        u0 += w * sbf0[o];
        u1 += w * sbf1[o];
    }
    g_u[n * 2 * C_DIM + c]         = u0;
    g_u[n * 2 * C_DIM + C_DIM + c] = u1;

    float t0 = blockSumBroadcast(b_v[c] * sbf0[c], sm8);
    float t1 = blockSumBroadcast(b_v[c] * sbf1[c], sm8);
    if (c == 0) { g_t[n * 2] = t0; g_t[n * 2 + 1] = t1; }
}

// ---------------------------------------------------------------------------
// K2b: attention probability per pixel (sigmoid of logit difference).
// ---------------------------------------------------------------------------
__global__ void k2b_probs(const float* __restrict__ x) {
    int n = blockIdx.y;
    int s = blockIdx.x * 256 + threadIdx.x;

    __shared__ float sud[C_DIM];
    sud[threadIdx.x] = g_u[n * 2 * C_DIM + threadIdx.x]
                     - g_u[n * 2 * C_DIM + C_DIM + threadIdx.x];
    __syncthreads();

    const float* xp = x + (size_t)n * C_DIM * S_DIM + s;
    float a = 0.f;
    #pragma unroll 8
    for (int cc = 0; cc < C_DIM; cc++)
        a += xp[(size_t)cc * S_DIM] * sud[cc];
    float d = a + (g_t[n * 2] - g_t[n * 2 + 1]);
    g_p[n * S_DIM + s] = 1.f / (1.f + expf(-d));
}

// ---------------------------------------------------------------------------
// K3: Y[c,s] = W_f[c,:]·X[:,s] + b_f[c] + gamma*(bf0[c]*p[s] + bf1[c]*(1-p[s]))
// 128x128 tile, BK=16, 256 threads.  Microtile: 4c x 16s per thread
// (tx = tid&7 selects s strips, ty = tid>>3 selects 4 c rows).
// Per k-step smem traffic per warp (128B/cyc units):
//   B: four LDS.128 at 16B lane stride ({0,32,64,96}+tx*4) -> banks 0..31
//      covered exactly once each -> 1 unit each = 4 (the 512B data floor).
//   A: two LDS.128 of duplicated pairs, 4 distinct addrs (8-lane broadcast)
//      -> 1 unit each = 2.
// Total 6 units vs 12 measured in R10 (L1=91.4%): L1 and FMA both ~ceiling.
// ---------------------------------------------------------------------------
__global__ __launch_bounds__(256) void k3_gemm(const float* __restrict__ x,
                                               const float* __restrict__ W_f,
                                               const float* __restrict__ b_f,
                                               const float* __restrict__ gamma,
                                               float* __restrict__ y) {
    int n  = blockIdx.z;
    int c0 = blockIdx.y * 128;
    int s0 = blockIdx.x * 128;
    int tid = threadIdx.x;
    int tx = tid & 7;     // s direction: four 4-wide strips at +0,+32,+64,+96
    int ty = tid >> 3;    // c direction: 4 rows (c = ty*4..ty*4+3)

    __shared__ __align__(16) float As2[2][16][AS_STRIDE]; // duplicated A pairs
    __shared__ __align__(16) float Bs [2][16][128];       // [buf][k][s]

    u64 acc2[4][8];   // [c offset][s pair]
    #pragma unroll
    for (int i = 0; i < 4; i++)
        #pragma unroll
        for (int j = 0; j < 8; j++) acc2[i][j] = 0ull;

    const float* xb = x + (size_t)n * C_DIM * S_DIM;

    int a_c0 = (tid >> 2);          // 0..63
    int a_k0 = (tid & 3) * 4;       // 0,4,8,12
    int b_k0 = (tid >> 5);          // 0..7
    int b_s0 = (tid & 31) * 4;      // 0..124

    // ---- preload tile 0 into buffer 0 ----
    #pragma unroll
    for (int r = 0; r < 2; r++) {
        int c_off = r * 64 + a_c0;
        float4 v = *(const float4*)&W_f[(size_t)(c0 + c_off) * C_DIM + a_k0];
        *(float2*)&As2[0][a_k0    ][2 * c_off] = make_float2(v.x, v.x);
        *(float2*)&As2[0][a_k0 + 1][2 * c_off] = make_float2(v.y, v.y);
        *(float2*)&As2[0][a_k0 + 2][2 * c_off] = make_float2(v.z, v.z);
        *(float2*)&As2[0][a_k0 + 3][2 * c_off] = make_float2(v.w, v.w);
    }
    #pragma unroll
    for (int r = 0; r < 2; r++) {
        int kr = r * 8 + b_k0;
        *(float4*)&Bs[0][kr][b_s0] =
            *(const float4*)&xb[(size_t)kr * S_DIM + s0 + b_s0];
    }
    __syncthreads();

    int cur = 0;
    for (int k0 = 0; k0 < C_DIM; k0 += 16) {
        // ---- prefetch next tile into registers ----
        float4 nA[2], nB[2];
        bool has_next = (k0 + 16) < C_DIM;
        if (has_next) {
            int kn = k0 + 16;
            #pragma unroll
            for (int r = 0; r < 2; r++) {
                int c_off = r * 64 + a_c0;
                nA[r] = *(const float4*)&W_f[(size_t)(c0 + c_off) * C_DIM + kn + a_k0];
                int kr = r * 8 + b_k0;
                nB[r] = *(const float4*)&xb[(size_t)(kn + kr) * S_DIM + s0 + b_s0];
            }
        }

        // ---- compute on current buffer (packed f32x2) ----
        #pragma unroll
        for (int k = 0; k < 16; k++) {
            // a: 4 duplicated pairs (c = ty*4..+3) -> two 16B broadcast loads
            const ulonglong2* apv = (const ulonglong2*)&As2[cur][k][ty * 8];
            ulonglong2 a01 = apv[0], a23 = apv[1];
            u64 ap[4] = {a01.x, a01.y, a23.x, a23.y};
            // b: four 16B loads at 16B lane stride -> conflict-free
            ulonglong2 t0 = *(const ulonglong2*)&Bs[cur][k][tx * 4];
            ulonglong2 t1 = *(const ulonglong2*)&Bs[cur][k][32 + tx * 4];
            ulonglong2 t2 = *(const ulonglong2*)&Bs[cur][k][64 + tx * 4];
            ulonglong2 t3 = *(const ulonglong2*)&Bs[cur][k][96 + tx * 4];
            u64 bp[8] = {t0.x, t0.y, t1.x, t1.y, t2.x, t2.y, t3.x, t3.y};
            #pragma unroll
            for (int i = 0; i < 4; i++)
                #pragma unroll
                for (int j = 0; j < 8; j++)
                    FMA_F32X2(acc2[i][j], ap[i], bp[j]);
        }

        // ---- commit prefetched tile into the other buffer ----
        if (has_next) {
            int nxt = cur ^ 1;
            #pragma unroll
            for (int r = 0; r < 2; r++) {
                int c_off = r * 64 + a_c0;
                float4 v = nA[r];
                *(float2*)&As2[nxt][a_k0    ][2 * c_off] = make_float2(v.x, v.x);
                *(float2*)&As2[nxt][a_k0 + 1][2 * c_off] = make_float2(v.y, v.y);
                *(float2*)&As2[nxt][a_k0 + 2][2 * c_off] = make_float2(v.z, v.z);
                *(float2*)&As2[nxt][a_k0 + 3][2 * c_off] = make_float2(v.w, v.w);
                int kr = r * 8 + b_k0;
                *(float4*)&Bs[nxt][kr][b_s0] = nB[r];
            }
            __syncthreads();
            cur = nxt;
        }
    }

    // ---- fused epilogue: 4 c rows x four 4-wide s strips ----
    float g = gamma[0];

    #pragma unroll
    for (int i = 0; i < 4; i++) {
        int c = c0 + ty * 4 + i;
        float f0 = g_bf[n * 2 * C_DIM + c];
        float f1 = g_bf[n * 2 * C_DIM + C_DIM + c];
        float bias = b_f[c];
        float* yp = y + ((size_t)(n * C_DIM + c)) * S_DIM + s0;
        #pragma unroll
        for (int st = 0; st < 4; st++) {
            u64 vlo = acc2[i][2 * st];
            u64 vhi = acc2[i][2 * st + 1];
            float o[4];
            o[0] = __uint_as_float((unsigned)(vlo & 0xffffffffull));
            o[1] = __uint_as_float((unsigned)(vlo >> 32));
            o[2] = __uint_as_float((unsigned)(vhi & 0xffffffffull));
            o[3] = __uint_as_float((unsigned)(vhi >> 32));
            int sb = st * 32 + tx * 4;
            const float* pp = &g_p[n * S_DIM + s0 + sb];
            float4 ov;
            float p0 = pp[0], p1 = pp[1], p2 = pp[2], p3 = pp[3];
            ov.x = o[0] + bias + g * (f0 * p0 + f1 * (1.f - p0));
            ov.y = o[1] + bias + g * (f0 * p1 + f1 * (1.f - p1));
            ov.z = o[2] + bias + g * (f0 * p2 + f1 * (1.f - p2));
            ov.w = o[3] + bias + g * (f0 * p3 + f1 * (1.f - p3));
            *(float4*)&yp[sb] = ov;
        }
    }
}

// ---------------------------------------------------------------------------
extern "C" void kernel_launch(void* const* d_in, const int* in_sizes, int n_in,
                              void* d_out, int out_size) {
    const float* x     = (const float*)d_in[0];
    const float* bg    = (const float*)d_in[1];
    const float* fg    = (const float*)d_in[2];
    const float* W_fb  = (const float*)d_in[3];
    const float* b_fb  = (const float*)d_in[4];
    const float* W_v   = (const float*)d_in[5];
    const float* b_v   = (const float*)d_in[6];
    const float* W_f   = (const float*)d_in[7];
    const float* b_f   = (const float*)d_in[8];
    const float* gamma = (const float*)d_in[9];
    float* y = (float*)d_out;

    int N = in_sizes[0] / (C_DIM * S_DIM);

    k1_masked_sums<<<dim3(32, N), 256>>>(x, bg, fg);
    k2_feats<<<N, 256>>>(bg, fg, W_fb, b_fb, W_v, b_v, N);
    k2b_probs<<<dim3(S_DIM / 256, N), 256>>>(x);
    k3_gemm<<<dim3(S_DIM / 128, C_DIM / 128, N), 256>>>(x, W_f, b_f, gamma, y);
}